// round 16
// baseline (speedup 1.0000x reference)
#include <cuda_runtime.h>
#include <cuda_bf16.h>
#include <cstdint>

#define NROWS_MAX 65536
typedef unsigned long long ull;

// scratch: left/right activations [n][0..31]=left, [n][32..63]=right
__device__ __align__(16) float g_lr[(size_t)NROWS_MAX * 64];
// pre-split Ws1, bf16, N-major, XOR-swizzled: [17 chunks][128 n][64 k]
__device__ __align__(16) __nv_bfloat16 g_whi[17 * 8192];
__device__ __align__(16) __nv_bfloat16 g_wlo[17 * 8192];
// pre-split Wa, bf16, N-major, XOR-swizzled: [17 chunks][32 n][64 k]
__device__ __align__(16) __nv_bfloat16 g_wahi[17 * 2048];
__device__ __align__(16) __nv_bfloat16 g_walo[17 * 2048];

// ---------- cp.async ----------
__device__ __forceinline__ uint32_t s2u(const void* p) {
    uint32_t a;
    asm("{ .reg .u64 t; cvta.to.shared.u64 t, %1; cvt.u32.u64 %0, t; }" : "=r"(a) : "l"(p));
    return a;
}
__device__ __forceinline__ void cpa16(uint32_t dst, const void* src) {
    asm volatile("cp.async.ca.shared.global [%0], [%1], 16;" :: "r"(dst), "l"(src));
}
__device__ __forceinline__ void cpa_commit() { asm volatile("cp.async.commit_group;"); }
template<int N> __device__ __forceinline__ void cpa_wait() {
    asm volatile("cp.async.wait_group %0;" :: "n"(N));
}
// ---------- tensor primitives ----------
__device__ __forceinline__ void ldsm4(uint32_t* r, uint32_t a) {
    asm volatile("ldmatrix.sync.aligned.m8n8.x4.shared.b16 {%0,%1,%2,%3}, [%4];"
        : "=r"(r[0]), "=r"(r[1]), "=r"(r[2]), "=r"(r[3]) : "r"(a));
}
__device__ __forceinline__ void mma_bf16(float* d, const uint32_t* a, const uint32_t* b) {
    asm volatile("mma.sync.aligned.m16n8k16.row.col.f32.bf16.bf16.f32 "
        "{%0,%1,%2,%3}, {%4,%5,%6,%7}, {%8,%9}, {%0,%1,%2,%3};"
        : "+f"(d[0]), "+f"(d[1]), "+f"(d[2]), "+f"(d[3])
        : "r"(a[0]), "r"(a[1]), "r"(a[2]), "r"(a[3]), "r"(b[0]), "r"(b[1]));
}
__device__ __forceinline__ void mma_bf16_c0(float* d, const uint32_t* a, const uint32_t* b) {
    asm volatile("mma.sync.aligned.m16n8k16.row.col.f32.bf16.bf16.f32 "
        "{%0,%1,%2,%3}, {%4,%5,%6,%7}, {%8,%9}, {%10,%11,%12,%13};"
        : "=f"(d[0]), "=f"(d[1]), "=f"(d[2]), "=f"(d[3])
        : "r"(a[0]), "r"(a[1]), "r"(a[2]), "r"(a[3]), "r"(b[0]), "r"(b[1]),
          "f"(0.f), "f"(0.f), "f"(0.f), "f"(0.f));
}
// split a pair of floats into packed bf16 hi / lo
__device__ __forceinline__ void split2(float f0, float f1, uint32_t& hp, uint32_t& lp) {
    asm("cvt.rn.bf16x2.f32 %0, %1, %2;" : "=r"(hp) : "f"(f1), "f"(f0));
    float b0 = __uint_as_float(hp << 16);
    float b1 = __uint_as_float(hp & 0xffff0000u);
    asm("cvt.rn.bf16x2.f32 %0, %1, %2;" : "=r"(lp) : "f"(f1 - b1), "f"(f0 - b0));
}

// =====================================================================
// Converters: split weights -> bf16 hi/lo, N-major swizzled
// =====================================================================
__global__ void k_conv(const float* __restrict__ Ws1) {
    int gid = blockIdx.x * 256 + threadIdx.x;
    if (gid >= 17 * 64 * 128) return;
    int s = gid >> 13, rem = gid & 8191;
    int k = rem >> 7, n = rem & 127;
    float w = Ws1[(s * 64 + k) * 128 + n];
    __nv_bfloat16 hi = __float2bfloat16(w);
    __nv_bfloat16 lo = __float2bfloat16(w - __bfloat162float(hi));
    uint32_t off = (uint32_t)s * 16384 + n * 128 + ((((k >> 3) ^ (n & 7))) << 4) + (k & 7) * 2;
    *(__nv_bfloat16*)((char*)g_whi + off) = hi;
    *(__nv_bfloat16*)((char*)g_wlo + off) = lo;
}
__global__ void k_conv_a(const float* __restrict__ Wa) {
    int gid = blockIdx.x * 256 + threadIdx.x;
    if (gid >= 17 * 64 * 32) return;
    int s = gid >> 11, rem = gid & 2047;
    int k = rem >> 5, n = rem & 31;
    float w = Wa[(s * 64 + k) * 32 + n];
    __nv_bfloat16 hi = __float2bfloat16(w);
    __nv_bfloat16 lo = __float2bfloat16(w - __bfloat162float(hi));
    uint32_t off = (uint32_t)s * 4096 + n * 128 + ((((k >> 3) ^ (n & 7))) << 4) + (k & 7) * 2;
    *(__nv_bfloat16*)((char*)g_wahi + off) = hi;
    *(__nv_bfloat16*)((char*)g_walo + off) = lo;
}

// =====================================================================
// Kernel A v2: factored bilinear MMA with register-resident v.
// F@Wa = [u|v]@W0a + sum_i diag(u_i)*(v @ Qa_i)
// =====================================================================
#define LB_LR    0
#define LB_AHI   65536
#define LB_ALO   98304
#define LB_B     131072
#define LB_UT    155648
#define LB_WN    188544
#define LB_BN    192640
#define LB_BA    192768
#define LB_SMEM  192896

__global__ __launch_bounds__(512, 1) void k_lrm(
    const float* __restrict__ concepts, const float* __restrict__ Wn,
    const float* __restrict__ bn, const float* __restrict__ ba,
    const void* __restrict__ idxp)
{
    extern __shared__ __align__(16) char sm[];
    float* LR = (float*)(sm + LB_LR);
    float* UT = (float*)(sm + LB_UT);
    uint32_t sb = s2u(sm);
    int tid = threadIdx.x;
    int wid = tid >> 5, lane = tid & 31;
    int n0 = blockIdx.x << 7;
    int halfc = tid >> 8, ec = tid & 255;

    #pragma unroll
    for (int p = 0; p < 2; ++p) {
        cpa16(sb + LB_B + p * 8192 + halfc * 4096 + ec * 16,
              (halfc ? (const char*)g_walo : (const char*)g_wahi) + (size_t)p * 4096 + ec * 16);
        cpa_commit();
    }

    {
        float* Wns = (float*)(sm + LB_WN);
        for (int e = tid; e < 1024; e += 512) Wns[e] = Wn[e];
        if (tid < 32) {
            ((float*)(sm + LB_BN))[tid] = bn[tid];
            ((float*)(sm + LB_BA))[tid] = ba[tid];
        }
    }

    const int* idx32 = (const int*)idxp;
    bool is64 = (idx32[1] == 0) & (idx32[3] == 0) & (idx32[5] == 0) & (idx32[7] == 0);
    const long long* idx64 = (const long long*)idxp;

    float* Atemp = (float*)(sm + LB_AHI);
    for (int e = tid; e < 4096; e += 512) {
        int row = e >> 5, col = e & 31;
        long long base = (long long)(n0 + row) * 4;
        long long ia = is64 ? idx64[base]     : (long long)idx32[base];
        long long ib = is64 ? idx64[base + 1] : (long long)idx32[base + 1];
        long long ic = is64 ? idx64[base + 2] : (long long)idx32[base + 2];
        long long id = is64 ? idx64[base + 3] : (long long)idx32[base + 3];
        float av = concepts[ia * 32 + col];
        float bv = concepts[ib * 32 + col];
        float cv = concepts[ic * 32 + col];
        float dv = concepts[id * 32 + col];
        Atemp[row * 32 + col]          = av;
        LR[row * 64 + 32 + col]        = bv;
        LR[8192 + row * 64 + col]      = cv;
        LR[8192 + row * 64 + 32 + col] = dv;
        UT[col * 257 + 128 + row]      = cv;
    }
    __syncthreads();

    {
        const float* Wns = (const float*)(sm + LB_WN);
        const float* bns = (const float*)(sm + LB_BN);
        for (int e = tid; e < 4096; e += 512) {
            int row = e >> 5, col = e & 31;
            float acc = bns[col];
            #pragma unroll
            for (int i = 0; i < 32; ++i)
                acc = fmaf(Atemp[row * 32 + i], Wns[i * 32 + col], acc);
            LR[row * 64 + col] = acc;
            UT[col * 257 + row] = acc;
        }
    }
    __syncthreads();

    #pragma unroll
    for (int it = 0; it < 16; ++it) {
        int p = it * 512 + tid;
        int row = p >> 5, t0 = (p & 31) * 2;
        const float* LRs = LR + (row >> 7) * 8192;
        int lrow = row & 127;
        float2 lv = *(const float2*)&LRs[lrow * 64 + t0];
        uint32_t hp, lp;
        split2(lv.x, lv.y, hp, lp);
        uint32_t off = row * 128 + ((((t0 >> 3) ^ (row & 7))) << 4) + (t0 & 7) * 2;
        *(uint32_t*)(sm + LB_AHI + off) = hp;
        *(uint32_t*)(sm + LB_ALO + off) = lp;
    }
    cpa_wait<1>();
    __syncthreads();

    cpa16(sb + LB_B + 2 * 8192 + halfc * 4096 + ec * 16,
          (halfc ? (const char*)g_walo : (const char*)g_wahi) + (size_t)2 * 4096 + ec * 16);
    cpa_commit();

    float acc[2][2][4];
    #pragma unroll
    for (int mt = 0; mt < 2; ++mt)
        #pragma unroll
        for (int nt = 0; nt < 2; ++nt)
            #pragma unroll
            for (int e = 0; e < 4; ++e) acc[mt][nt][e] = 0.f;

    int m0w = (wid >> 1) * 32, n0w = (wid & 1) * 16;
    int li = lane & 7, lt = lane >> 3;
    int rA_off = li + ((lt & 1) << 3);
    int segA_h = lt >> 1;
    int hB = lt & 1;
    int lobB = (lt >> 1) * 4096;
    int ql = lane >> 2;

    uint32_t rfh[2][2][4], rfl[2][2][4];
    {
        uint32_t Bb = sb + LB_B;
        #pragma unroll
        for (int ks = 0; ks < 4; ++ks) {
            uint32_t bf[2][4];
            #pragma unroll
            for (int nt = 0; nt < 2; ++nt) {
                int row = n0w + nt * 8 + li;
                uint32_t addr = Bb + lobB + row * 128 + ((((2 * ks + hB) ^ (row & 7))) << 4);
                ldsm4(bf[nt], addr);
            }
            #pragma unroll
            for (int mt = 0; mt < 2; ++mt) {
                int row = m0w + mt * 16 + rA_off;
                int seg = 2 * ks + segA_h;
                uint32_t addr = sb + LB_AHI + row * 128 + (((seg ^ (row & 7))) << 4);
                uint32_t ah[4], al[4];
                ldsm4(ah, addr);
                ldsm4(al, addr + 32768);
                if (ks >= 2) {
                    #pragma unroll
                    for (int e = 0; e < 4; ++e) {
                        rfh[mt][ks - 2][e] = ah[e];
                        rfl[mt][ks - 2][e] = al[e];
                    }
                }
                #pragma unroll
                for (int nt = 0; nt < 2; ++nt) {
                    mma_bf16(acc[mt][nt], ah, bf[nt]);
                    mma_bf16(acc[mt][nt], ah, bf[nt] + 2);
                    mma_bf16(acc[mt][nt], al, bf[nt]);
                }
            }
        }
    }

    for (int s = 1; s < 17; ++s) {
        cpa_wait<1>();
        __syncthreads();
        if (s + 2 < 17) {
            cpa16(sb + LB_B + ((s + 2) % 3) * 8192 + halfc * 4096 + ec * 16,
                  (halfc ? (const char*)g_walo : (const char*)g_wahi) + (size_t)(s + 2) * 4096 + ec * 16);
        }
        cpa_commit();

        uint32_t Bb = sb + LB_B + (s % 3) * 8192;
        #pragma unroll
        for (int h = 0; h < 2; ++h) {
            int i = 2 * (s - 1) + h;
            uint32_t bf[2][2][4];
            #pragma unroll
            for (int nt = 0; nt < 2; ++nt) {
                #pragma unroll
                for (int k2 = 0; k2 < 2; ++k2) {
                    int row = n0w + nt * 8 + li;
                    uint32_t addr = Bb + lobB + row * 128
                                  + ((((4 * h + 2 * k2 + hB) ^ (row & 7))) << 4);
                    ldsm4(bf[nt][k2], addr);
                }
            }
            #pragma unroll
            for (int mt = 0; mt < 2; ++mt) {
                float l0 = UT[i * 257 + m0w + mt * 16 + ql];
                float l1 = UT[i * 257 + m0w + mt * 16 + ql + 8];
                #pragma unroll
                for (int nt = 0; nt < 2; ++nt) {
                    float P0[4], P1[4];
                    mma_bf16_c0(P0, rfh[mt][0], bf[nt][0]);
                    mma_bf16(P0, rfh[mt][0], bf[nt][0] + 2);
                    mma_bf16(P0, rfl[mt][0], bf[nt][0]);
                    mma_bf16_c0(P1, rfh[mt][1], bf[nt][1]);
                    mma_bf16(P1, rfh[mt][1], bf[nt][1] + 2);
                    mma_bf16(P1, rfl[mt][1], bf[nt][1]);
                    acc[mt][nt][0] = fmaf(l0, P0[0], fmaf(l0, P1[0], acc[mt][nt][0]));
                    acc[mt][nt][1] = fmaf(l0, P0[1], fmaf(l0, P1[1], acc[mt][nt][1]));
                    acc[mt][nt][2] = fmaf(l1, P0[2], fmaf(l1, P1[2], acc[mt][nt][2]));
                    acc[mt][nt][3] = fmaf(l1, P0[3], fmaf(l1, P1[3], acc[mt][nt][3]));
                }
            }
        }
    }

    const float* bas = (const float*)(sm + LB_BA);
    int c2 = (lane & 3) * 2;
    #pragma unroll
    for (int mt = 0; mt < 2; ++mt) {
        #pragma unroll
        for (int nt = 0; nt < 2; ++nt) {
            int col = n0w + nt * 8 + c2;
            float bax = bas[col], bay = bas[col + 1];
            int gr0 = m0w + mt * 16 + ql;
            int gr1 = gr0 + 8;
            float* d = acc[mt][nt];
            size_t o0 = (size_t)(n0 + (gr0 & 127)) * 64 + (gr0 >> 7) * 32 + col;
            size_t o1 = (size_t)(n0 + (gr1 & 127)) * 64 + (gr1 >> 7) * 32 + col;
            g_lr[o0]     = d[0] + bax;
            g_lr[o0 + 1] = d[1] + bay;
            g_lr[o1]     = d[2] + bax;
            g_lr[o1 + 1] = d[3] + bay;
        }
    }
}

// =====================================================================
// Kernel B v2: factored bilinear MMA with register-resident R.
// =====================================================================
#define SM_LR   0
#define SM_AHI  32768
#define SM_ALO  49152
#define SM_B    65536
#define SM_LT   163840
#define SM_BS1  180736
#define SM_W2   181248
#define SM_DS   181760
#define KM_SMEM 183808

__global__ __launch_bounds__(512, 1) void k_main(
    const float* __restrict__ bs1, const float* __restrict__ Ws2,
    const float* __restrict__ bs2, float* __restrict__ out)
{
    extern __shared__ __align__(16) char sm[];
    float* LR = (float*)(sm + SM_LR);
    float* LT = (float*)(sm + SM_LT);
    uint32_t sb = s2u(sm);
    int tid = threadIdx.x;
    int wid = tid >> 5, lane = tid & 31;
    int n0 = blockIdx.x << 7;

    #pragma unroll
    for (int p = 0; p < 2; ++p) {
        #pragma unroll
        for (int qq = 0; qq < 2; ++qq) {
            int e = qq * 512 + tid;
            cpa16(sb + SM_B + p * 32768 + e * 16,         (const char*)g_whi + (size_t)p * 16384 + e * 16);
            cpa16(sb + SM_B + p * 32768 + 16384 + e * 16, (const char*)g_wlo + (size_t)p * 16384 + e * 16);
        }
        cpa_commit();
    }

    #pragma unroll
    for (int it = 0; it < 4; ++it) {
        int e4 = it * 512 + tid;
        int r = e4 >> 4, qq = e4 & 15;
        float4 v = *(const float4*)&g_lr[(size_t)(n0 + r) * 64 + qq * 4];
        *(float4*)&LR[r * 64 + qq * 4] = v;
        if (qq < 8) {
            int k0 = qq * 4;
            LT[(k0 + 0) * 132 + r] = v.x;
            LT[(k0 + 1) * 132 + r] = v.y;
            LT[(k0 + 2) * 132 + r] = v.z;
            LT[(k0 + 3) * 132 + r] = v.w;
        }
    }
    if (tid < 128) {
        ((float*)(sm + SM_BS1))[tid] = bs1[tid];
        ((float*)(sm + SM_W2))[tid]  = Ws2[tid];
    }
    __syncthreads();

    #pragma unroll
    for (int it = 0; it < 8; ++it) {
        int p = it * 512 + tid;
        int row = p >> 5, t0 = (p & 31) * 2;
        float2 lv = *(const float2*)&LR[row * 64 + t0];
        uint32_t hp, lp;
        split2(lv.x, lv.y, hp, lp);
        uint32_t off = row * 128 + ((((t0 >> 3) ^ (row & 7))) << 4) + (t0 & 7) * 2;
        *(uint32_t*)(sm + SM_AHI + off) = hp;
        *(uint32_t*)(sm + SM_ALO + off) = lp;
    }
    cpa_wait<1>();
    __syncthreads();

    #pragma unroll
    for (int qq = 0; qq < 2; ++qq) {
        int e = qq * 512 + tid;
        cpa16(sb + SM_B + 2 * 32768 + e * 16,         (const char*)g_whi + (size_t)2 * 16384 + e * 16);
        cpa16(sb + SM_B + 2 * 32768 + 16384 + e * 16, (const char*)g_wlo + (size_t)2 * 16384 + e * 16);
    }
    cpa_commit();

    float acc[2][4][4];
    #pragma unroll
    for (int mt = 0; mt < 2; ++mt)
        #pragma unroll
        for (int nt = 0; nt < 4; ++nt)
            #pragma unroll
            for (int e = 0; e < 4; ++e) acc[mt][nt][e] = 0.f;

    int m0w = (wid >> 2) * 32, n0w = (wid & 3) * 32;
    int li = lane & 7, lt = lane >> 3;
    int rA_off = li + ((lt & 1) << 3);
    int segA_h = lt >> 1;
    int hB = lt & 1;
    int lobB = (lt >> 1) * 16384;
    int ql = lane >> 2;

    uint32_t rfh[2][2][4], rfl[2][2][4];
    {
        uint32_t Bb = sb + SM_B;
        #pragma unroll
        for (int ks = 0; ks < 4; ++ks) {
            uint32_t bf[4][4];
            #pragma unroll
            for (int nt = 0; nt < 4; ++nt) {
                int row = n0w + nt * 8 + li;
                uint32_t addr = Bb + lobB + row * 128 + ((((2 * ks + hB) ^ (row & 7))) << 4);
                ldsm4(bf[nt], addr);
            }
            #pragma unroll
            for (int mt = 0; mt < 2; ++mt) {
                int row = m0w + mt * 16 + rA_off;
                int seg = 2 * ks + segA_h;
                uint32_t addr = sb + SM_AHI + row * 128 + (((seg ^ (row & 7))) << 4);
                uint32_t ah[4], al[4];
                ldsm4(ah, addr);
                ldsm4(al, addr + 16384);
                if (ks >= 2) {
                    #pragma unroll
                    for (int e = 0; e < 4; ++e) {
                        rfh[mt][ks - 2][e] = ah[e];
                        rfl[mt][ks - 2][e] = al[e];
                    }
                }
                #pragma unroll
                for (int nt = 0; nt < 4; ++nt) {
                    mma_bf16(acc[mt][nt], ah, bf[nt]);
                    mma_bf16(acc[mt][nt], ah, bf[nt] + 2);
                    mma_bf16(acc[mt][nt], al, bf[nt]);
                }
            }
        }
    }

    for (int s = 1; s < 17; ++s) {
        cpa_wait<1>();
        __syncthreads();
        if (s + 2 < 17) {
            #pragma unroll
            for (int qq = 0; qq < 2; ++qq) {
                int e = qq * 512 + tid;
                cpa16(sb + SM_B + ((s + 2) % 3) * 32768 + e * 16,
                      (const char*)g_whi + (size_t)(s + 2) * 16384 + e * 16);
                cpa16(sb + SM_B + ((s + 2) % 3) * 32768 + 16384 + e * 16,
                      (const char*)g_wlo + (size_t)(s + 2) * 16384 + e * 16);
            }
        }
        cpa_commit();

        uint32_t Bb = sb + SM_B + (s % 3) * 32768;
        #pragma unroll
        for (int h = 0; h < 2; ++h) {
            int i = 2 * (s - 1) + h;
            uint32_t bf[4][2][4];
            #pragma unroll
            for (int nt = 0; nt < 4; ++nt) {
                #pragma unroll
                for (int k2 = 0; k2 < 2; ++k2) {
                    int row = n0w + nt * 8 + li;
                    uint32_t addr = Bb + lobB + row * 128
                                  + ((((4 * h + 2 * k2 + hB) ^ (row & 7))) << 4);
                    ldsm4(bf[nt][k2], addr);
                }
            }
            #pragma unroll
            for (int mt = 0; mt < 2; ++mt) {
                float l0 = LT[i * 132 + m0w + mt * 16 + ql];
                float l1 = LT[i * 132 + m0w + mt * 16 + ql + 8];
                #pragma unroll
                for (int nt = 0; nt < 4; ++nt) {
                    float P0[4], P1[4];
                    mma_bf16_c0(P0, rfh[mt][0], bf[nt][0]);
                    mma_bf16(P0, rfh[mt][0], bf[nt][0] + 2);
                    mma_bf16(P0, rfl[mt][0], bf[nt][0]);
                    mma_bf16_c0(P1, rfh[mt][1], bf[nt][1]);
                    mma_bf16(P1, rfh[mt][1], bf[nt][1] + 2);
                    mma_bf16(P1, rfl[mt][1], bf[nt][1]);
                    acc[mt][nt][0] = fmaf(l0, P0[0], fmaf(l0, P1[0], acc[mt][nt][0]));
                    acc[mt][nt][1] = fmaf(l0, P0[1], fmaf(l0, P1[1], acc[mt][nt][1]));
                    acc[mt][nt][2] = fmaf(l1, P0[2], fmaf(l1, P1[2], acc[mt][nt][2]));
                    acc[mt][nt][3] = fmaf(l1, P0[3], fmaf(l1, P1[3], acc[mt][nt][3]));
                }
            }
        }
    }

    const float* bs1s = (const float*)(sm + SM_BS1);
    const float* w2s  = (const float*)(sm + SM_W2);
    float* Dsum = (float*)(sm + SM_DS);
    int c2 = (lane & 3) * 2;
    float bias2 = bs2[0];
    #pragma unroll
    for (int mt = 0; mt < 2; ++mt) {
        float s0 = 0.f, s1 = 0.f;
        #pragma unroll
        for (int nt = 0; nt < 4; ++nt) {
            int col = n0w + nt * 8 + c2;
            float2 bv = *(const float2*)&bs1s[col];
            float2 wv = *(const float2*)&w2s[col];
            float* d = acc[mt][nt];
            float x0 = d[0] + bv.x, x1 = d[1] + bv.y;
            float x2 = d[2] + bv.x, x3 = d[3] + bv.y;
            float h0 = x0 > 0.f ? x0 : expm1f(x0);
            float h1 = x1 > 0.f ? x1 : expm1f(x1);
            float h2 = x2 > 0.f ? x2 : expm1f(x2);
            float h3 = x3 > 0.f ? x3 : expm1f(x3);
            s0 = fmaf(h0, wv.x, fmaf(h1, wv.y, s0));
            s1 = fmaf(h2, wv.x, fmaf(h3, wv.y, s1));
        }
        s0 += __shfl_xor_sync(0xffffffffu, s0, 1);
        s0 += __shfl_xor_sync(0xffffffffu, s0, 2);
        s1 += __shfl_xor_sync(0xffffffffu, s1, 1);
        s1 += __shfl_xor_sync(0xffffffffu, s1, 2);
        if ((lane & 3) == 0) {
            int row = m0w + mt * 16 + ql;
            Dsum[row * 4 + (wid & 3)] = s0;
            Dsum[(row + 8) * 4 + (wid & 3)] = s1;
        }
    }
    __syncthreads();
    if (tid < 128) {
        float v = Dsum[tid * 4] + Dsum[tid * 4 + 1] + Dsum[tid * 4 + 2] + Dsum[tid * 4 + 3];
        out[n0 + tid] = v + bias2;
    }
}

extern "C" void kernel_launch(void* const* d_in, const int* in_sizes, int n_in,
                              void* d_out, int out_size)
{
    const float* concepts = (const float*)d_in[0];
    const float* Wn  = (const float*)d_in[1];
    const float* bn  = (const float*)d_in[2];
    const float* Wa  = (const float*)d_in[3];
    const float* ba  = (const float*)d_in[4];
    const float* Ws1 = (const float*)d_in[5];
    const float* bs1 = (const float*)d_in[6];
    const float* Ws2 = (const float*)d_in[7];
    const float* bs2 = (const float*)d_in[8];
    const void*  idx = d_in[9];
    int nrows = in_sizes[9] / 4;

    static int inited = 0;
    if (!inited) {
        cudaFuncSetAttribute(k_main, cudaFuncAttributeMaxDynamicSharedMemorySize, KM_SMEM);
        cudaFuncSetAttribute(k_lrm,  cudaFuncAttributeMaxDynamicSharedMemorySize, LB_SMEM);
        inited = 1;
    }

    k_conv<<<(17 * 64 * 128 + 255) / 256, 256>>>(Ws1);
    k_conv_a<<<(17 * 64 * 32 + 255) / 256, 256>>>(Wa);
    k_lrm<<<nrows / 128, 512, LB_SMEM>>>(concepts, Wn, bn, ba, idx);
    k_main<<<nrows / 128, 512, KM_SMEM>>>(bs1, Ws2, bs2, (float*)d_out);
}

// round 17
// speedup vs baseline: 1.0509x; 1.0509x over previous
#include <cuda_runtime.h>
#include <cuda_bf16.h>
#include <cstdint>

#define NROWS_MAX 65536
typedef unsigned long long ull;

// scratch: left/right activations [n][0..31]=left, [n][32..63]=right
__device__ __align__(16) float g_lr[(size_t)NROWS_MAX * 64];
// pre-split Ws1, bf16, N-major, XOR-swizzled: [17 chunks][128 n][64 k]
__device__ __align__(16) __nv_bfloat16 g_whi[17 * 8192];
__device__ __align__(16) __nv_bfloat16 g_wlo[17 * 8192];
// pre-split Wa, bf16, N-major, XOR-swizzled: [17 chunks][32 n][64 k]
__device__ __align__(16) __nv_bfloat16 g_wahi[17 * 2048];
__device__ __align__(16) __nv_bfloat16 g_walo[17 * 2048];

// ---------- cp.async ----------
__device__ __forceinline__ uint32_t s2u(const void* p) {
    uint32_t a;
    asm("{ .reg .u64 t; cvta.to.shared.u64 t, %1; cvt.u32.u64 %0, t; }" : "=r"(a) : "l"(p));
    return a;
}
__device__ __forceinline__ void cpa16(uint32_t dst, const void* src) {
    asm volatile("cp.async.ca.shared.global [%0], [%1], 16;" :: "r"(dst), "l"(src));
}
__device__ __forceinline__ void cpa_commit() { asm volatile("cp.async.commit_group;"); }
template<int N> __device__ __forceinline__ void cpa_wait() {
    asm volatile("cp.async.wait_group %0;" :: "n"(N));
}
// ---------- tensor primitives ----------
__device__ __forceinline__ void ldsm4(uint32_t* r, uint32_t a) {
    asm volatile("ldmatrix.sync.aligned.m8n8.x4.shared.b16 {%0,%1,%2,%3}, [%4];"
        : "=r"(r[0]), "=r"(r[1]), "=r"(r[2]), "=r"(r[3]) : "r"(a));
}
__device__ __forceinline__ void mma_bf16(float* d, const uint32_t* a, const uint32_t* b) {
    asm volatile("mma.sync.aligned.m16n8k16.row.col.f32.bf16.bf16.f32 "
        "{%0,%1,%2,%3}, {%4,%5,%6,%7}, {%8,%9}, {%0,%1,%2,%3};"
        : "+f"(d[0]), "+f"(d[1]), "+f"(d[2]), "+f"(d[3])
        : "r"(a[0]), "r"(a[1]), "r"(a[2]), "r"(a[3]), "r"(b[0]), "r"(b[1]));
}
__device__ __forceinline__ void mma_bf16_c0(float* d, const uint32_t* a, const uint32_t* b) {
    asm volatile("mma.sync.aligned.m16n8k16.row.col.f32.bf16.bf16.f32 "
        "{%0,%1,%2,%3}, {%4,%5,%6,%7}, {%8,%9}, {%10,%11,%12,%13};"
        : "=f"(d[0]), "=f"(d[1]), "=f"(d[2]), "=f"(d[3])
        : "r"(a[0]), "r"(a[1]), "r"(a[2]), "r"(a[3]), "r"(b[0]), "r"(b[1]),
          "f"(0.f), "f"(0.f), "f"(0.f), "f"(0.f));
}
// split a pair of floats into packed bf16 hi / lo
__device__ __forceinline__ void split2(float f0, float f1, uint32_t& hp, uint32_t& lp) {
    asm("cvt.rn.bf16x2.f32 %0, %1, %2;" : "=r"(hp) : "f"(f1), "f"(f0));
    float b0 = __uint_as_float(hp << 16);
    float b1 = __uint_as_float(hp & 0xffff0000u);
    asm("cvt.rn.bf16x2.f32 %0, %1, %2;" : "=r"(lp) : "f"(f1 - b1), "f"(f0 - b0));
}

// =====================================================================
// Merged converter: split Ws1 and Wa -> bf16 hi/lo, N-major swizzled
// =====================================================================
#define NS1 (17 * 64 * 128)
#define NSA (17 * 64 * 32)
__global__ void k_convm(const float* __restrict__ Ws1, const float* __restrict__ Wa) {
    int gid = blockIdx.x * 256 + threadIdx.x;
    if (gid < NS1) {
        int s = gid >> 13, rem = gid & 8191;
        int k = rem >> 7, n = rem & 127;
        float w = Ws1[(s * 64 + k) * 128 + n];
        __nv_bfloat16 hi = __float2bfloat16(w);
        __nv_bfloat16 lo = __float2bfloat16(w - __bfloat162float(hi));
        uint32_t off = (uint32_t)s * 16384 + n * 128 + ((((k >> 3) ^ (n & 7))) << 4) + (k & 7) * 2;
        *(__nv_bfloat16*)((char*)g_whi + off) = hi;
        *(__nv_bfloat16*)((char*)g_wlo + off) = lo;
    } else {
        int g = gid - NS1;
        if (g >= NSA) return;
        int s = g >> 11, rem = g & 2047;
        int k = rem >> 5, n = rem & 31;
        float w = Wa[(s * 64 + k) * 32 + n];
        __nv_bfloat16 hi = __float2bfloat16(w);
        __nv_bfloat16 lo = __float2bfloat16(w - __bfloat162float(hi));
        uint32_t off = (uint32_t)s * 4096 + n * 128 + ((((k >> 3) ^ (n & 7))) << 4) + (k & 7) * 2;
        *(__nv_bfloat16*)((char*)g_wahi + off) = hi;
        *(__nv_bfloat16*)((char*)g_walo + off) = lo;
    }
}

// =====================================================================
// Kernel A v2 (R14 form): factored bilinear MMA with register-resident v.
// F@Wa = [u|v]@W0a + sum_i diag(u_i)*(v @ Qa_i)
// =====================================================================
#define LB_LR    0
#define LB_AHI   65536
#define LB_ALO   98304
#define LB_B     131072
#define LB_UT    155648
#define LB_WN    188544
#define LB_BN    192640
#define LB_BA    192768
#define LB_SMEM  192896

__global__ __launch_bounds__(512, 1) void k_lrm(
    const float* __restrict__ concepts, const float* __restrict__ Wn,
    const float* __restrict__ bn, const float* __restrict__ ba,
    const void* __restrict__ idxp)
{
    extern __shared__ __align__(16) char sm[];
    float* LR = (float*)(sm + LB_LR);
    float* UT = (float*)(sm + LB_UT);
    uint32_t sb = s2u(sm);
    int tid = threadIdx.x;
    int wid = tid >> 5, lane = tid & 31;
    int n0 = blockIdx.x << 7;
    int halfc = tid >> 8, ec = tid & 255;

    #pragma unroll
    for (int p = 0; p < 2; ++p) {
        cpa16(sb + LB_B + p * 8192 + halfc * 4096 + ec * 16,
              (halfc ? (const char*)g_walo : (const char*)g_wahi) + (size_t)p * 4096 + ec * 16);
        cpa_commit();
    }

    {
        float* Wns = (float*)(sm + LB_WN);
        for (int e = tid; e < 1024; e += 512) Wns[e] = Wn[e];
        if (tid < 32) {
            ((float*)(sm + LB_BN))[tid] = bn[tid];
            ((float*)(sm + LB_BA))[tid] = ba[tid];
        }
    }

    const int* idx32 = (const int*)idxp;
    bool is64 = (idx32[1] == 0) & (idx32[3] == 0) & (idx32[5] == 0) & (idx32[7] == 0);
    const long long* idx64 = (const long long*)idxp;

    float* Atemp = (float*)(sm + LB_AHI);
    for (int e = tid; e < 4096; e += 512) {
        int row = e >> 5, col = e & 31;
        long long base = (long long)(n0 + row) * 4;
        long long ia = is64 ? idx64[base]     : (long long)idx32[base];
        long long ib = is64 ? idx64[base + 1] : (long long)idx32[base + 1];
        long long ic = is64 ? idx64[base + 2] : (long long)idx32[base + 2];
        long long id = is64 ? idx64[base + 3] : (long long)idx32[base + 3];
        float av = concepts[ia * 32 + col];
        float bv = concepts[ib * 32 + col];
        float cv = concepts[ic * 32 + col];
        float dv = concepts[id * 32 + col];
        Atemp[row * 32 + col]          = av;
        LR[row * 64 + 32 + col]        = bv;
        LR[8192 + row * 64 + col]      = cv;
        LR[8192 + row * 64 + 32 + col] = dv;
        UT[col * 257 + 128 + row]      = cv;
    }
    __syncthreads();

    {
        const float* Wns = (const float*)(sm + LB_WN);
        const float* bns = (const float*)(sm + LB_BN);
        for (int e = tid; e < 4096; e += 512) {
            int row = e >> 5, col = e & 31;
            float acc = bns[col];
            #pragma unroll
            for (int i = 0; i < 32; ++i)
                acc = fmaf(Atemp[row * 32 + i], Wns[i * 32 + col], acc);
            LR[row * 64 + col] = acc;
            UT[col * 257 + row] = acc;
        }
    }
    __syncthreads();

    #pragma unroll
    for (int it = 0; it < 16; ++it) {
        int p = it * 512 + tid;
        int row = p >> 5, t0 = (p & 31) * 2;
        const float* LRs = LR + (row >> 7) * 8192;
        int lrow = row & 127;
        float2 lv = *(const float2*)&LRs[lrow * 64 + t0];
        uint32_t hp, lp;
        split2(lv.x, lv.y, hp, lp);
        uint32_t off = row * 128 + ((((t0 >> 3) ^ (row & 7))) << 4) + (t0 & 7) * 2;
        *(uint32_t*)(sm + LB_AHI + off) = hp;
        *(uint32_t*)(sm + LB_ALO + off) = lp;
    }
    cpa_wait<1>();
    __syncthreads();

    cpa16(sb + LB_B + 2 * 8192 + halfc * 4096 + ec * 16,
          (halfc ? (const char*)g_walo : (const char*)g_wahi) + (size_t)2 * 4096 + ec * 16);
    cpa_commit();

    float acc[2][2][4];
    #pragma unroll
    for (int mt = 0; mt < 2; ++mt)
        #pragma unroll
        for (int nt = 0; nt < 2; ++nt)
            #pragma unroll
            for (int e = 0; e < 4; ++e) acc[mt][nt][e] = 0.f;

    int m0w = (wid >> 1) * 32, n0w = (wid & 1) * 16;
    int li = lane & 7, lt = lane >> 3;
    int rA_off = li + ((lt & 1) << 3);
    int segA_h = lt >> 1;
    int hB = lt & 1;
    int lobB = (lt >> 1) * 4096;
    int ql = lane >> 2;

    uint32_t rfh[2][2][4], rfl[2][2][4];
    {
        uint32_t Bb = sb + LB_B;
        #pragma unroll
        for (int ks = 0; ks < 4; ++ks) {
            uint32_t bf[2][4];
            #pragma unroll
            for (int nt = 0; nt < 2; ++nt) {
                int row = n0w + nt * 8 + li;
                uint32_t addr = Bb + lobB + row * 128 + ((((2 * ks + hB) ^ (row & 7))) << 4);
                ldsm4(bf[nt], addr);
            }
            #pragma unroll
            for (int mt = 0; mt < 2; ++mt) {
                int row = m0w + mt * 16 + rA_off;
                int seg = 2 * ks + segA_h;
                uint32_t addr = sb + LB_AHI + row * 128 + (((seg ^ (row & 7))) << 4);
                uint32_t ah[4], al[4];
                ldsm4(ah, addr);
                ldsm4(al, addr + 32768);
                if (ks >= 2) {
                    #pragma unroll
                    for (int e = 0; e < 4; ++e) {
                        rfh[mt][ks - 2][e] = ah[e];
                        rfl[mt][ks - 2][e] = al[e];
                    }
                }
                #pragma unroll
                for (int nt = 0; nt < 2; ++nt) {
                    mma_bf16(acc[mt][nt], ah, bf[nt]);
                    mma_bf16(acc[mt][nt], ah, bf[nt] + 2);
                    mma_bf16(acc[mt][nt], al, bf[nt]);
                }
            }
        }
    }

    for (int s = 1; s < 17; ++s) {
        cpa_wait<1>();
        __syncthreads();
        if (s + 2 < 17) {
            cpa16(sb + LB_B + ((s + 2) % 3) * 8192 + halfc * 4096 + ec * 16,
                  (halfc ? (const char*)g_walo : (const char*)g_wahi) + (size_t)(s + 2) * 4096 + ec * 16);
        }
        cpa_commit();

        uint32_t Bb = sb + LB_B + (s % 3) * 8192;
        #pragma unroll
        for (int h = 0; h < 2; ++h) {
            int i = 2 * (s - 1) + h;
            uint32_t bf[2][2][4];
            #pragma unroll
            for (int nt = 0; nt < 2; ++nt) {
                #pragma unroll
                for (int k2 = 0; k2 < 2; ++k2) {
                    int row = n0w + nt * 8 + li;
                    uint32_t addr = Bb + lobB + row * 128
                                  + ((((4 * h + 2 * k2 + hB) ^ (row & 7))) << 4);
                    ldsm4(bf[nt][k2], addr);
                }
            }
            #pragma unroll
            for (int mt = 0; mt < 2; ++mt) {
                float l0 = UT[i * 257 + m0w + mt * 16 + ql];
                float l1 = UT[i * 257 + m0w + mt * 16 + ql + 8];
                #pragma unroll
                for (int nt = 0; nt < 2; ++nt) {
                    float P[4];
                    mma_bf16_c0(P, rfh[mt][0], bf[nt][0]);
                    mma_bf16(P, rfh[mt][0], bf[nt][0] + 2);
                    mma_bf16(P, rfl[mt][0], bf[nt][0]);
                    mma_bf16(P, rfh[mt][1], bf[nt][1]);
                    mma_bf16(P, rfh[mt][1], bf[nt][1] + 2);
                    mma_bf16(P, rfl[mt][1], bf[nt][1]);
                    acc[mt][nt][0] = fmaf(l0, P[0], acc[mt][nt][0]);
                    acc[mt][nt][1] = fmaf(l0, P[1], acc[mt][nt][1]);
                    acc[mt][nt][2] = fmaf(l1, P[2], acc[mt][nt][2]);
                    acc[mt][nt][3] = fmaf(l1, P[3], acc[mt][nt][3]);
                }
            }
        }
    }

    const float* bas = (const float*)(sm + LB_BA);
    int c2 = (lane & 3) * 2;
    #pragma unroll
    for (int mt = 0; mt < 2; ++mt) {
        #pragma unroll
        for (int nt = 0; nt < 2; ++nt) {
            int col = n0w + nt * 8 + c2;
            float bax = bas[col], bay = bas[col + 1];
            int gr0 = m0w + mt * 16 + ql;
            int gr1 = gr0 + 8;
            float* d = acc[mt][nt];
            size_t o0 = (size_t)(n0 + (gr0 & 127)) * 64 + (gr0 >> 7) * 32 + col;
            size_t o1 = (size_t)(n0 + (gr1 & 127)) * 64 + (gr1 >> 7) * 32 + col;
            g_lr[o0]     = d[0] + bax;
            g_lr[o0 + 1] = d[1] + bay;
            g_lr[o1]     = d[2] + bax;
            g_lr[o1 + 1] = d[3] + bay;
        }
    }
}

// =====================================================================
// Kernel B v2 (R14 form): factored bilinear MMA with register-resident R.
// =====================================================================
#define SM_LR   0
#define SM_AHI  32768
#define SM_ALO  49152
#define SM_B    65536
#define SM_LT   163840
#define SM_BS1  180736
#define SM_W2   181248
#define SM_DS   181760
#define KM_SMEM 183808

__global__ __launch_bounds__(512, 1) void k_main(
    const float* __restrict__ bs1, const float* __restrict__ Ws2,
    const float* __restrict__ bs2, float* __restrict__ out)
{
    extern __shared__ __align__(16) char sm[];
    float* LR = (float*)(sm + SM_LR);
    float* LT = (float*)(sm + SM_LT);
    uint32_t sb = s2u(sm);
    int tid = threadIdx.x;
    int wid = tid >> 5, lane = tid & 31;
    int n0 = blockIdx.x << 7;

    #pragma unroll
    for (int p = 0; p < 2; ++p) {
        #pragma unroll
        for (int qq = 0; qq < 2; ++qq) {
            int e = qq * 512 + tid;
            cpa16(sb + SM_B + p * 32768 + e * 16,         (const char*)g_whi + (size_t)p * 16384 + e * 16);
            cpa16(sb + SM_B + p * 32768 + 16384 + e * 16, (const char*)g_wlo + (size_t)p * 16384 + e * 16);
        }
        cpa_commit();
    }

    #pragma unroll
    for (int it = 0; it < 4; ++it) {
        int e4 = it * 512 + tid;
        int r = e4 >> 4, qq = e4 & 15;
        float4 v = *(const float4*)&g_lr[(size_t)(n0 + r) * 64 + qq * 4];
        *(float4*)&LR[r * 64 + qq * 4] = v;
        if (qq < 8) {
            int k0 = qq * 4;
            LT[(k0 + 0) * 132 + r] = v.x;
            LT[(k0 + 1) * 132 + r] = v.y;
            LT[(k0 + 2) * 132 + r] = v.z;
            LT[(k0 + 3) * 132 + r] = v.w;
        }
    }
    if (tid < 128) {
        ((float*)(sm + SM_BS1))[tid] = bs1[tid];
        ((float*)(sm + SM_W2))[tid]  = Ws2[tid];
    }
    __syncthreads();

    #pragma unroll
    for (int it = 0; it < 8; ++it) {
        int p = it * 512 + tid;
        int row = p >> 5, t0 = (p & 31) * 2;
        float2 lv = *(const float2*)&LR[row * 64 + t0];
        uint32_t hp, lp;
        split2(lv.x, lv.y, hp, lp);
        uint32_t off = row * 128 + ((((t0 >> 3) ^ (row & 7))) << 4) + (t0 & 7) * 2;
        *(uint32_t*)(sm + SM_AHI + off) = hp;
        *(uint32_t*)(sm + SM_ALO + off) = lp;
    }
    cpa_wait<1>();
    __syncthreads();

    #pragma unroll
    for (int qq = 0; qq < 2; ++qq) {
        int e = qq * 512 + tid;
        cpa16(sb + SM_B + 2 * 32768 + e * 16,         (const char*)g_whi + (size_t)2 * 16384 + e * 16);
        cpa16(sb + SM_B + 2 * 32768 + 16384 + e * 16, (const char*)g_wlo + (size_t)2 * 16384 + e * 16);
    }
    cpa_commit();

    float acc[2][4][4];
    #pragma unroll
    for (int mt = 0; mt < 2; ++mt)
        #pragma unroll
        for (int nt = 0; nt < 4; ++nt)
            #pragma unroll
            for (int e = 0; e < 4; ++e) acc[mt][nt][e] = 0.f;

    int m0w = (wid >> 2) * 32, n0w = (wid & 3) * 32;
    int li = lane & 7, lt = lane >> 3;
    int rA_off = li + ((lt & 1) << 3);
    int segA_h = lt >> 1;
    int hB = lt & 1;
    int lobB = (lt >> 1) * 16384;
    int ql = lane >> 2;

    uint32_t rfh[2][2][4], rfl[2][2][4];
    {
        uint32_t Bb = sb + SM_B;
        #pragma unroll
        for (int ks = 0; ks < 4; ++ks) {
            uint32_t bf[4][4];
            #pragma unroll
            for (int nt = 0; nt < 4; ++nt) {
                int row = n0w + nt * 8 + li;
                uint32_t addr = Bb + lobB + row * 128 + ((((2 * ks + hB) ^ (row & 7))) << 4);
                ldsm4(bf[nt], addr);
            }
            #pragma unroll
            for (int mt = 0; mt < 2; ++mt) {
                int row = m0w + mt * 16 + rA_off;
                int seg = 2 * ks + segA_h;
                uint32_t addr = sb + SM_AHI + row * 128 + (((seg ^ (row & 7))) << 4);
                uint32_t ah[4], al[4];
                ldsm4(ah, addr);
                ldsm4(al, addr + 16384);
                if (ks >= 2) {
                    #pragma unroll
                    for (int e = 0; e < 4; ++e) {
                        rfh[mt][ks - 2][e] = ah[e];
                        rfl[mt][ks - 2][e] = al[e];
                    }
                }
                #pragma unroll
                for (int nt = 0; nt < 4; ++nt) {
                    mma_bf16(acc[mt][nt], ah, bf[nt]);
                    mma_bf16(acc[mt][nt], ah, bf[nt] + 2);
                    mma_bf16(acc[mt][nt], al, bf[nt]);
                }
            }
        }
    }

    for (int s = 1; s < 17; ++s) {
        cpa_wait<1>();
        __syncthreads();
        if (s + 2 < 17) {
            #pragma unroll
            for (int qq = 0; qq < 2; ++qq) {
                int e = qq * 512 + tid;
                cpa16(sb + SM_B + ((s + 2) % 3) * 32768 + e * 16,
                      (const char*)g_whi + (size_t)(s + 2) * 16384 + e * 16);
                cpa16(sb + SM_B + ((s + 2) % 3) * 32768 + 16384 + e * 16,
                      (const char*)g_wlo + (size_t)(s + 2) * 16384 + e * 16);
            }
        }
        cpa_commit();

        uint32_t Bb = sb + SM_B + (s % 3) * 32768;
        #pragma unroll
        for (int h = 0; h < 2; ++h) {
            int i = 2 * (s - 1) + h;
            uint32_t bf[4][2][4];
            #pragma unroll
            for (int nt = 0; nt < 4; ++nt) {
                #pragma unroll
                for (int k2 = 0; k2 < 2; ++k2) {
                    int row = n0w + nt * 8 + li;
                    uint32_t addr = Bb + lobB + row * 128
                                  + ((((4 * h + 2 * k2 + hB) ^ (row & 7))) << 4);
                    ldsm4(bf[nt][k2], addr);
                }
            }
            #pragma unroll
            for (int mt = 0; mt < 2; ++mt) {
                float l0 = LT[i * 132 + m0w + mt * 16 + ql];
                float l1 = LT[i * 132 + m0w + mt * 16 + ql + 8];
                #pragma unroll
                for (int nt = 0; nt < 4; ++nt) {
                    float P[4];
                    mma_bf16_c0(P, rfh[mt][0], bf[nt][0]);
                    mma_bf16(P, rfh[mt][0], bf[nt][0] + 2);
                    mma_bf16(P, rfl[mt][0], bf[nt][0]);
                    mma_bf16(P, rfh[mt][1], bf[nt][1]);
                    mma_bf16(P, rfh[mt][1], bf[nt][1] + 2);
                    mma_bf16(P, rfl[mt][1], bf[nt][1]);
                    acc[mt][nt][0] = fmaf(l0, P[0], acc[mt][nt][0]);
                    acc[mt][nt][1] = fmaf(l0, P[1], acc[mt][nt][1]);
                    acc[mt][nt][2] = fmaf(l1, P[2], acc[mt][nt][2]);
                    acc[mt][nt][3] = fmaf(l1, P[3], acc[mt][nt][3]);
                }
            }
        }
    }

    const float* bs1s = (const float*)(sm + SM_BS1);
    const float* w2s  = (const float*)(sm + SM_W2);
    float* Dsum = (float*)(sm + SM_DS);
    int c2 = (lane & 3) * 2;
    float bias2 = bs2[0];
    #pragma unroll
    for (int mt = 0; mt < 2; ++mt) {
        float s0 = 0.f, s1 = 0.f;
        #pragma unroll
        for (int nt = 0; nt < 4; ++nt) {
            int col = n0w + nt * 8 + c2;
            float2 bv = *(const float2*)&bs1s[col];
            float2 wv = *(const float2*)&w2s[col];
            float* d = acc[mt][nt];
            float x0 = d[0] + bv.x, x1 = d[1] + bv.y;
            float x2 = d[2] + bv.x, x3 = d[3] + bv.y;
            float h0 = x0 > 0.f ? x0 : expm1f(x0);
            float h1 = x1 > 0.f ? x1 : expm1f(x1);
            float h2 = x2 > 0.f ? x2 : expm1f(x2);
            float h3 = x3 > 0.f ? x3 : expm1f(x3);
            s0 = fmaf(h0, wv.x, fmaf(h1, wv.y, s0));
            s1 = fmaf(h2, wv.x, fmaf(h3, wv.y, s1));
        }
        s0 += __shfl_xor_sync(0xffffffffu, s0, 1);
        s0 += __shfl_xor_sync(0xffffffffu, s0, 2);
        s1 += __shfl_xor_sync(0xffffffffu, s1, 1);
        s1 += __shfl_xor_sync(0xffffffffu, s1, 2);
        if ((lane & 3) == 0) {
            int row = m0w + mt * 16 + ql;
            Dsum[row * 4 + (wid & 3)] = s0;
            Dsum[(row + 8) * 4 + (wid & 3)] = s1;
        }
    }
    __syncthreads();
    if (tid < 128) {
        float v = Dsum[tid * 4] + Dsum[tid * 4 + 1] + Dsum[tid * 4 + 2] + Dsum[tid * 4 + 3];
        out[n0 + tid] = v + bias2;
    }
}

extern "C" void kernel_launch(void* const* d_in, const int* in_sizes, int n_in,
                              void* d_out, int out_size)
{
    const float* concepts = (const float*)d_in[0];
    const float* Wn  = (const float*)d_in[1];
    const float* bn  = (const float*)d_in[2];
    const float* Wa  = (const float*)d_in[3];
    const float* ba  = (const float*)d_in[4];
    const float* Ws1 = (const float*)d_in[5];
    const float* bs1 = (const float*)d_in[6];
    const float* Ws2 = (const float*)d_in[7];
    const float* bs2 = (const float*)d_in[8];
    const void*  idx = d_in[9];
    int nrows = in_sizes[9] / 4;

    static int inited = 0;
    if (!inited) {
        cudaFuncSetAttribute(k_main, cudaFuncAttributeMaxDynamicSharedMemorySize, KM_SMEM);
        cudaFuncSetAttribute(k_lrm,  cudaFuncAttributeMaxDynamicSharedMemorySize, LB_SMEM);
        inited = 1;
    }

    k_convm<<<(NS1 + NSA + 255) / 256, 256>>>(Ws1, Wa);
    k_lrm<<<nrows / 128, 512, LB_SMEM>>>(concepts, Wn, bn, ba, idx);
    k_main<<<nrows / 128, 512, KM_SMEM>>>(bs1, Ws2, bs2, (float*)d_out);
}